// round 1
// baseline (speedup 1.0000x reference)
#include <cuda_runtime.h>
#include <cstdint>

// Problem constants
#define BB 64
#define SS 512
#define HH 768
#define EE 128
#define TT_ 4
#define NT 5
#define H4 192   // H/4 float4 lanes

// Scratch (no allocs allowed)
__device__ int   g_inv_ptr[SS + 1];
__device__ int   g_inv_e[EE * TT_];
__device__ float g_rowcoef[BB * SS * 8];   // {at0..at4, ac, 0, 0} per (b,s)

// ---------------------------------------------------------------------------
// P0: invert ent_tokens (E*T flat) into CSR: token s -> list of entity ids
// ---------------------------------------------------------------------------
__global__ void build_csr_kernel(const int* __restrict__ ent_tokens) {
    __shared__ int cnt[SS];
    __shared__ int offs[SS];
    int tid = threadIdx.x;              // 512 threads, one per flat (e,t)
    cnt[tid] = 0;
    __syncthreads();
    int tok = ent_tokens[tid];
    atomicAdd(&cnt[tok], 1);
    __syncthreads();
    if (tid == 0) {
        int acc = 0;
        for (int s = 0; s < SS; s++) {
            g_inv_ptr[s] = acc;
            offs[s] = acc;
            acc += cnt[s];
        }
        g_inv_ptr[SS] = acc;
    }
    __syncthreads();
    int pos = atomicAdd(&offs[tok], 1);
    g_inv_e[pos] = tid >> 2;            // entity id = flat/T
}

// ---------------------------------------------------------------------------
// P1: per-(b,s) scalar coefficients: type histogram (5) + sum of confidences
// ---------------------------------------------------------------------------
__global__ void rowcoef_kernel(const int* __restrict__ types,     // [B,E]
                               const float* __restrict__ conf) {  // [B,E]
    int idx = blockIdx.x * blockDim.x + threadIdx.x;
    if (idx >= BB * SS) return;
    int b = idx >> 9;       // /512
    int s = idx & (SS - 1);
    float at[NT] = {0.f, 0.f, 0.f, 0.f, 0.f};
    float ac = 0.f;
    int beg = g_inv_ptr[s], end = g_inv_ptr[s + 1];
    for (int k = beg; k < end; k++) {
        int e = g_inv_e[k];
        int ty = types[b * EE + e];
        at[ty] += 1.f;
        ac += conf[b * EE + e];
    }
    float4* o = reinterpret_cast<float4*>(&g_rowcoef[(size_t)idx * 8]);
    o[0] = make_float4(at[0], at[1], at[2], at[3]);
    o[1] = make_float4(at[4], ac, 0.f, 0.f);
}

// ---------------------------------------------------------------------------
// B: streaming enhance: out = hidden + sum_ty at[ty]*(TT[ty]+cb) + ac*cw
//    Each thread owns a fixed float4 h-lane; tables live in registers.
// ---------------------------------------------------------------------------
__global__ void __launch_bounds__(H4) enhance_kernel(
    const float* __restrict__ hidden,
    const float* __restrict__ type_table,   // [NT,H]
    const float* __restrict__ conf_w,       // [H]
    const float* __restrict__ conf_b,       // [H]
    float* __restrict__ out_enh) {
    int tid = threadIdx.x;                  // 0..191
    int h = tid * 4;

    float4 cb4 = *reinterpret_cast<const float4*>(conf_b + h);
    float4 cw4 = *reinterpret_cast<const float4*>(conf_w + h);
    float4 ttc[NT];
#pragma unroll
    for (int ty = 0; ty < NT; ty++) {
        float4 v = *reinterpret_cast<const float4*>(type_table + ty * HH + h);
        ttc[ty] = make_float4(v.x + cb4.x, v.y + cb4.y, v.z + cb4.z, v.w + cb4.w);
    }

    for (int r = blockIdx.x; r < BB * SS; r += gridDim.x) {
        const float4* cf = reinterpret_cast<const float4*>(&g_rowcoef[(size_t)r * 8]);
        float4 c0 = __ldg(cf);
        float4 c1 = __ldg(cf + 1);
        float4 v = *reinterpret_cast<const float4*>(hidden + (size_t)r * HH + h);
        float a0 = c0.x, a1 = c0.y, a2 = c0.z, a3 = c0.w, a4 = c1.x, ac = c1.y;
        v.x += a0 * ttc[0].x + a1 * ttc[1].x + a2 * ttc[2].x + a3 * ttc[3].x + a4 * ttc[4].x + ac * cw4.x;
        v.y += a0 * ttc[0].y + a1 * ttc[1].y + a2 * ttc[2].y + a3 * ttc[3].y + a4 * ttc[4].y + ac * cw4.y;
        v.z += a0 * ttc[0].z + a1 * ttc[1].z + a2 * ttc[2].z + a3 * ttc[3].z + a4 * ttc[4].z + ac * cw4.z;
        v.w += a0 * ttc[0].w + a1 * ttc[1].w + a2 * ttc[2].w + a3 * ttc[3].w + a4 * ttc[4].w + ac * cw4.w;
        *reinterpret_cast<float4*>(out_enh + (size_t)r * HH + h) = v;
    }
}

// ---------------------------------------------------------------------------
// C: entity_embeddings[b,e,:] = 0.25 * sum_t enhanced[b, tok(e,t), :]
// ---------------------------------------------------------------------------
__global__ void __launch_bounds__(H4) gather_mean_kernel(
    const int* __restrict__ ent_tokens,     // [E,T]
    const float* __restrict__ enh,          // [B,S,H]
    float* __restrict__ out_emb) {          // [B,E,H]
    int tid = threadIdx.x;
    int h = tid * 4;
    for (int r = blockIdx.x; r < BB * EE; r += gridDim.x) {
        int b = r >> 7;          // /128
        int e = r & (EE - 1);
        const float* base = enh + (size_t)b * SS * HH + h;
        float4 acc = make_float4(0.f, 0.f, 0.f, 0.f);
#pragma unroll
        for (int t = 0; t < TT_; t++) {
            int s = __ldg(&ent_tokens[e * TT_ + t]);
            float4 v = *reinterpret_cast<const float4*>(base + (size_t)s * HH);
            acc.x += v.x; acc.y += v.y; acc.z += v.z; acc.w += v.w;
        }
        acc.x *= 0.25f; acc.y *= 0.25f; acc.z *= 0.25f; acc.w *= 0.25f;
        *reinterpret_cast<float4*>(out_emb + (size_t)r * HH + h) = acc;
    }
}

// ---------------------------------------------------------------------------
// Launch: inputs in metadata order:
// 0 hidden_states (B,S,H) f32 | 1 entity_types (B,E) i32 | 2 entity_confidences (B,E) f32
// 3 ent_tokens (E,T) i32 | 4 type_table (NT,H) f32 | 5 conf_w (1,H) f32 | 6 conf_b (H) f32
// Output: enhanced (B,S,H) then entity_embeddings (B,E,H), concatenated.
// ---------------------------------------------------------------------------
extern "C" void kernel_launch(void* const* d_in, const int* in_sizes, int n_in,
                              void* d_out, int out_size) {
    const float* hidden   = (const float*)d_in[0];
    const int*   types    = (const int*)d_in[1];
    const float* conf     = (const float*)d_in[2];
    const int*   ent_tok  = (const int*)d_in[3];
    const float* ttab     = (const float*)d_in[4];
    const float* conf_w   = (const float*)d_in[5];
    const float* conf_b   = (const float*)d_in[6];

    float* out_enh = (float*)d_out;
    float* out_emb = out_enh + (size_t)BB * SS * HH;

    build_csr_kernel<<<1, EE * TT_>>>(ent_tok);
    rowcoef_kernel<<<(BB * SS + 255) / 256, 256>>>(types, conf);
    enhance_kernel<<<1184, H4>>>(hidden, ttab, conf_w, conf_b, out_enh);
    gather_mean_kernel<<<4096, H4>>>(ent_tok, out_enh, out_emb);
}